// round 1
// baseline (speedup 1.0000x reference)
#include <cuda_runtime.h>
#include <cuda_bf16.h>

#define D 512
#define H 128
#define NROW 262143               // path rows
#define MBLK 64
#define NBLK ((NROW + MBLK - 1) / MBLK)   // 4096
#define GRID1 152
#define THREADS1 256

// ---------------- scratch (no allocations allowed) ----------------
__device__ float g_base[H];
__device__ float g_aggp[GRID1 * D];
__device__ float g_attnp[GRID1];
__device__ float g_comb[2 * D];
__device__ float g_p3[16 * D];
__device__ float g_gate[D];
__device__ float g_hidden[D];
__device__ float g_p5[8 * D];

// ---------------- smem layout for main kernel ----------------
#define SWT_STR 520   // bf16 elems per row (512 + 8 pad -> 1040B stride, conflict-free)
#define SA_STR  520
#define OFF_SWT  0
#define OFF_SA   (H * SWT_STR * 2)                 // 133120
#define OFF_PART (OFF_SA + MBLK * SA_STR * 2)      // 199680
#define OFF_ATTN (OFF_PART + MBLK * 4 * 4)         // 200704
#define OFF_BASE (OFF_ATTN + MBLK * 4)             // 200960
#define OFF_W2   (OFF_BASE + H * 4)                // 201472
#define OFF_TOT  (OFF_W2 + H * 4)                  // 201984
#define SMEM_SZ  (OFF_TOT + 16)

__device__ __forceinline__ void mma16816(float c[4], const unsigned a[4], const unsigned b[2]) {
    asm("mma.sync.aligned.m16n8k16.row.col.f32.bf16.bf16.f32 "
        "{%0,%1,%2,%3}, {%4,%5,%6,%7}, {%8,%9}, {%0,%1,%2,%3};\n"
        : "+f"(c[0]), "+f"(c[1]), "+f"(c[2]), "+f"(c[3])
        : "r"(a[0]), "r"(a[1]), "r"(a[2]), "r"(a[3]), "r"(b[0]), "r"(b[1]));
}

// ---------------- K0: base[j] = target @ aW1[:D] + ab1 ----------------
__global__ void k_base(const float* __restrict__ f, const float* __restrict__ aW1,
                       const float* __restrict__ ab1) {
    __shared__ float red[512];
    int tid = threadIdx.x;           // 512 threads
    int j = tid & 127;
    int part = tid >> 7;             // 0..3
    float acc = 0.f;
    int k0 = part * 128;
    for (int k = k0; k < k0 + 128; k++) acc += f[k] * aW1[k * H + j];
    red[tid] = acc;
    __syncthreads();
    if (tid < 128)
        g_base[tid] = red[tid] + red[tid + 128] + red[tid + 256] + red[tid + 384] + ab1[tid];
}

// ---------------- K1: fused copy + GEMM + attn + weighted-sum ----------------
__global__ void __launch_bounds__(THREADS1, 1)
k_main(const float* __restrict__ features, const float* __restrict__ aW1,
       const float* __restrict__ aW2, const float* __restrict__ ab2,
       float* __restrict__ out) {
    extern __shared__ char smem[];
    __nv_bfloat16* sWt = (__nv_bfloat16*)(smem + OFF_SWT);   // [128][520] W^T (n-major)
    __nv_bfloat16* sA  = (__nv_bfloat16*)(smem + OFF_SA);    // [64][520] row tile
    float* sPart = (float*)(smem + OFF_PART);                // [64][4]
    float* sAttn = (float*)(smem + OFF_ATTN);                // [64]
    float* sBase = (float*)(smem + OFF_BASE);                // [128]
    float* sW2   = (float*)(smem + OFF_W2);                  // [128]
    float* sTot  = (float*)(smem + OFF_TOT);

    int tid = threadIdx.x;

    // Load W = aW1[D:2D, :] transposed into smem as bf16 (coalesced global reads)
    for (int idx = tid; idx < D * H; idx += THREADS1) {
        int k = idx >> 7, n = idx & 127;
        sWt[n * SWT_STR + k] = __float2bfloat16(aW1[(D + k) * H + n]);
    }
    for (int j = tid; j < H; j += THREADS1) { sBase[j] = g_base[j]; sW2[j] = aW2[j]; }
    if (tid == 0) *sTot = 0.f;
    __syncthreads();

    int warp = tid >> 5, lane = tid & 31;
    int g = lane >> 2, tg = lane & 3;
    int wm = warp >> 2, wn = warp & 3;    // 2 m-groups x 4 n-groups of warps

    // hoist this thread's 8 (base, w2) column values
    float baseR[8], w2R[8];
#pragma unroll
    for (int nt = 0; nt < 4; nt++) {
        int col = wn * 32 + nt * 8 + tg * 2;
        baseR[nt * 2] = sBase[col];     baseR[nt * 2 + 1] = sBase[col + 1];
        w2R[nt * 2]   = sW2[col];       w2R[nt * 2 + 1]   = sW2[col + 1];
    }
    float ab2v = ab2[0];
    float agg0 = 0.f, agg1 = 0.f;       // this thread's agg columns: 2*tid, 2*tid+1

    for (int blk = blockIdx.x; blk < NBLK; blk += gridDim.x) {
        long rowbase = (long)blk * MBLK;   // path-row index base

        // ---- load 64 rows, stream-copy to out, convert to bf16 tile ----
#pragma unroll 4
        for (int i = tid; i < MBLK * 128; i += THREADS1) {
            int r = i >> 7;          // row in tile
            int c4 = i & 127;        // float4 column
            long prow = rowbase + r;
            if (prow < NROW) {
                const float4* src = (const float4*)(features + (prow + 1) * (long)D) + c4;
                float4 v = __ldcs(src);
                __stcs((float4*)(out + (prow + 1) * (long)D) + c4, v);
                __nv_bfloat162 lo = __floats2bfloat162_rn(v.x, v.y);
                __nv_bfloat162 hi = __floats2bfloat162_rn(v.z, v.w);
                uint2 pk;
                pk.x = *(unsigned*)&lo; pk.y = *(unsigned*)&hi;
                *(uint2*)(sA + r * SA_STR + c4 * 4) = pk;
            } else {
                *(uint2*)(sA + r * SA_STR + c4 * 4) = make_uint2(0u, 0u);
            }
        }
        __syncthreads();

        // ---- GEMM: (64 x 512) @ (512 x 128), warp tile 32x32 ----
        float c[2][4][4];
#pragma unroll
        for (int mt = 0; mt < 2; mt++)
#pragma unroll
            for (int nt = 0; nt < 4; nt++)
#pragma unroll
                for (int q = 0; q < 4; q++) c[mt][nt][q] = 0.f;

        for (int k0 = 0; k0 < D; k0 += 16) {
            unsigned aF[2][4], bF[4][2];
#pragma unroll
            for (int mt = 0; mt < 2; mt++) {
                const __nv_bfloat16* ap = sA + (wm * 32 + mt * 16 + g) * SA_STR + k0 + tg * 2;
                aF[mt][0] = *(const unsigned*)ap;
                aF[mt][1] = *(const unsigned*)(ap + 8 * SA_STR);
                aF[mt][2] = *(const unsigned*)(ap + 8);
                aF[mt][3] = *(const unsigned*)(ap + 8 * SA_STR + 8);
            }
#pragma unroll
            for (int nt = 0; nt < 4; nt++) {
                const __nv_bfloat16* bp = sWt + (wn * 32 + nt * 8 + g) * SWT_STR + k0 + tg * 2;
                bF[nt][0] = *(const unsigned*)bp;
                bF[nt][1] = *(const unsigned*)(bp + 8);
            }
#pragma unroll
            for (int mt = 0; mt < 2; mt++)
#pragma unroll
                for (int nt = 0; nt < 4; nt++)
                    mma16816(c[mt][nt], aF[mt], bF[nt]);
        }

        // ---- epilogue: partial  sum_cols relu(base+h)*w2  per row ----
#pragma unroll
        for (int mt = 0; mt < 2; mt++) {
            float pe = 0.f, po = 0.f;
#pragma unroll
            for (int nt = 0; nt < 4; nt++) {
                pe += fmaxf(baseR[nt * 2]     + c[mt][nt][0], 0.f) * w2R[nt * 2];
                pe += fmaxf(baseR[nt * 2 + 1] + c[mt][nt][1], 0.f) * w2R[nt * 2 + 1];
                po += fmaxf(baseR[nt * 2]     + c[mt][nt][2], 0.f) * w2R[nt * 2];
                po += fmaxf(baseR[nt * 2 + 1] + c[mt][nt][3], 0.f) * w2R[nt * 2 + 1];
            }
            pe += __shfl_xor_sync(0xffffffffu, pe, 1);
            pe += __shfl_xor_sync(0xffffffffu, pe, 2);
            po += __shfl_xor_sync(0xffffffffu, po, 1);
            po += __shfl_xor_sync(0xffffffffu, po, 2);
            if (tg == 0) {
                int row = wm * 32 + mt * 16 + g;
                sPart[row * 4 + wn] = pe;
                sPart[(row + 8) * 4 + wn] = po;
            }
        }
        __syncthreads();

        // ---- attn = sigmoid(. + ab2), masked for tail ----
        if (tid < MBLK) {
            float s = sPart[tid * 4] + sPart[tid * 4 + 1] + sPart[tid * 4 + 2] + sPart[tid * 4 + 3] + ab2v;
            float a = 1.f / (1.f + __expf(-s));
            if (rowbase + tid >= NROW) a = 0.f;
            sAttn[tid] = a;
        }
        __syncthreads();

        // attn-sum reduction (fixed order -> deterministic)
        if (tid < 32) {
            float v = sAttn[tid] + sAttn[tid + 32];
#pragma unroll
            for (int o = 16; o; o >>= 1) v += __shfl_xor_sync(0xffffffffu, v, o);
            if (tid == 0) *sTot += v;
        }

        // ---- agg += attn_r * row_r  (this thread: cols 2*tid, 2*tid+1) ----
#pragma unroll 8
        for (int r = 0; r < MBLK; r++) {
            float a = sAttn[r];
            __nv_bfloat162 v = *(__nv_bfloat162*)(sA + r * SA_STR + tid * 2);
            agg0 += a * __bfloat162float(v.x);
            agg1 += a * __bfloat162float(v.y);
        }
        __syncthreads();   // protect sA/sAttn before next iteration overwrites
    }

    g_aggp[blockIdx.x * D + 2 * tid]     = agg0;
    g_aggp[blockIdx.x * D + 2 * tid + 1] = agg1;
    if (tid == 0) g_attnp[blockIdx.x] = *sTot;
}

// ---------------- K2: reduce partials, build comb = [target, agg/s] ----------------
__global__ void k_reduce(const float* __restrict__ features) {
    __shared__ float sS;
    int j = threadIdx.x;   // 512
    float acc = 0.f;
    for (int i = 0; i < GRID1; i++) acc += g_aggp[i * D + j];
    if (j == 0) {
        float s = 0.f;
        for (int i = 0; i < GRID1; i++) s += g_attnp[i];
        sS = s;
    }
    __syncthreads();
    float s = sS;
    g_comb[j] = features[j];                       // target
    g_comb[D + j] = (s > 0.f) ? acc / s : acc;     // agg
}

// ---------------- K3: partial dots for gate (gW) and hidden (uW1) ----------------
__global__ void k_mid(const float* __restrict__ gW, const float* __restrict__ uW1) {
    __shared__ float sc[128];
    int b = blockIdx.x;                 // 0..15
    const float* W = (b < 8) ? gW : uW1;
    int ks = (b & 7) * 128;
    for (int i = threadIdx.x; i < 128; i += 256) sc[i] = g_comb[ks + i];
    __syncthreads();
    int c0 = threadIdx.x, c1 = threadIdx.x + 256;
    float a0 = 0.f, a1 = 0.f;
    for (int kk = 0; kk < 128; kk++) {
        float cv = sc[kk];
        const float* row = W + (ks + kk) * D;
        a0 += cv * row[c0];
        a1 += cv * row[c1];
    }
    g_p3[b * D + c0] = a0;
    g_p3[b * D + c1] = a1;
}

// ---------------- K4: gate = sigmoid(.+gb), hidden = relu(.+ub1) ----------------
__global__ void k_act(const float* __restrict__ gb, const float* __restrict__ ub1) {
    int j = threadIdx.x;   // 512
    float gs = 0.f, hs = 0.f;
    for (int b = 0; b < 8; b++)  gs += g_p3[b * D + j];
    for (int b = 8; b < 16; b++) hs += g_p3[b * D + j];
    g_gate[j] = 1.f / (1.f + __expf(-(gs + gb[j])));
    g_hidden[j] = fmaxf(hs + ub1[j], 0.f);
}

// ---------------- K5: partial dots for upd (uW2) ----------------
__global__ void k_upd(const float* __restrict__ uW2) {
    __shared__ float sh[64];
    int b = blockIdx.x;       // 0..7
    int ks = b * 64;
    for (int i = threadIdx.x; i < 64; i += 256) sh[i] = g_hidden[ks + i];
    __syncthreads();
    int c0 = threadIdx.x, c1 = threadIdx.x + 256;
    float a0 = 0.f, a1 = 0.f;
    for (int kk = 0; kk < 64; kk++) {
        float hv = sh[kk];
        const float* row = uW2 + (ks + kk) * D;
        a0 += hv * row[c0];
        a1 += hv * row[c1];
    }
    g_p5[b * D + c0] = a0;
    g_p5[b * D + c1] = a1;
}

// ---------------- K6: out row 0 = target + gate * (upd + ub2) ----------------
__global__ void k_fin(const float* __restrict__ features, const float* __restrict__ ub2,
                      float* __restrict__ out) {
    int j = threadIdx.x;   // 512
    float u = 0.f;
    for (int b = 0; b < 8; b++) u += g_p5[b * D + j];
    u += ub2[0];
    out[j] = features[j] + g_gate[j] * u;
}

extern "C" void kernel_launch(void* const* d_in, const int* in_sizes, int n_in,
                              void* d_out, int out_size) {
    const float* features = (const float*)d_in[0];
    const float* aW1 = (const float*)d_in[1];
    const float* ab1 = (const float*)d_in[2];
    const float* aW2 = (const float*)d_in[3];
    const float* ab2 = (const float*)d_in[4];
    const float* uW1 = (const float*)d_in[5];
    const float* ub1 = (const float*)d_in[6];
    const float* uW2 = (const float*)d_in[7];
    const float* ub2 = (const float*)d_in[8];
    const float* gW  = (const float*)d_in[9];
    const float* gb  = (const float*)d_in[10];
    float* out = (float*)d_out;

    cudaFuncSetAttribute(k_main, cudaFuncAttributeMaxDynamicSharedMemorySize, SMEM_SZ);

    k_base<<<1, 512>>>(features, aW1, ab1);
    k_main<<<GRID1, THREADS1, SMEM_SZ>>>(features, aW1, aW2, ab2, out);
    k_reduce<<<1, 512>>>(features);
    k_mid<<<16, 256>>>(gW, uW1);
    k_act<<<1, 512>>>(gb, ub1);
    k_upd<<<8, 256>>>(uW2);
    k_fin<<<1, 512>>>(features, ub2, out);
}

// round 2
// speedup vs baseline: 2.0906x; 2.0906x over previous
#include <cuda_runtime.h>
#include <cuda_bf16.h>

#define D 512
#define H 128
#define NROW 262143               // path rows
#define MBLK 32
#define NBLK ((NROW + MBLK - 1) / MBLK)   // 8192
#define GRID1 152
#define THREADS1 256

// ---------------- scratch (no allocations allowed) ----------------
__device__ float g_basep[16 * H];
__device__ float g_aggp[GRID1 * D];
__device__ float g_attnp[GRID1];
__device__ float g_comb[2 * D];
__device__ float g_p3[16 * D];
__device__ float g_gate[D];
__device__ float g_hidden[D];
__device__ float g_p5[8 * D];

// ---------------- smem layout for main kernel ----------------
#define SWT_STR 520   // bf16 elems per row (1040B stride -> conflict-free ldmatrix)
#define SA_STR  520
#define OFF_SWT  0
#define OFF_SA   (H * SWT_STR * 2)                 // 133120
#define OFF_PART (OFF_SA + MBLK * SA_STR * 2)      // 166400
#define OFF_ATTN (OFF_PART + MBLK * 4 * 4)         // 166912
#define OFF_BASE (OFF_ATTN + MBLK * 4)             // 167040
#define OFF_W2   (OFF_BASE + H * 4)                // 167552
#define OFF_TOT  (OFF_W2 + H * 4)                  // 168064
#define SMEM_SZ  (OFF_TOT + 16)

__device__ __forceinline__ void mma16816(float c[4], const unsigned a[4],
                                         unsigned b0, unsigned b1) {
    asm("mma.sync.aligned.m16n8k16.row.col.f32.bf16.bf16.f32 "
        "{%0,%1,%2,%3}, {%4,%5,%6,%7}, {%8,%9}, {%0,%1,%2,%3};\n"
        : "+f"(c[0]), "+f"(c[1]), "+f"(c[2]), "+f"(c[3])
        : "r"(a[0]), "r"(a[1]), "r"(a[2]), "r"(a[3]), "r"(b0), "r"(b1));
}

__device__ __forceinline__ void ldsm4(unsigned r[4], unsigned addr) {
    asm volatile("ldmatrix.sync.aligned.m8n8.x4.shared.b16 {%0,%1,%2,%3}, [%4];"
        : "=r"(r[0]), "=r"(r[1]), "=r"(r[2]), "=r"(r[3]) : "r"(addr));
}

// ---------------- K0: partial base[j] = target @ aW1[:D] (16-way split) ----------------
__global__ void k_basep(const float* __restrict__ f, const float* __restrict__ aW1) {
    int b = blockIdx.x;        // 16 blocks
    int j = threadIdx.x;       // 128 threads
    int k0 = b * 32;
    float acc = 0.f;
    for (int k = k0; k < k0 + 32; k++) acc += f[k] * aW1[k * H + j];
    g_basep[b * H + j] = acc;
}

// ---------------- K1: fused copy + GEMM + attn + weighted-sum ----------------
__global__ void __launch_bounds__(THREADS1, 1)
k_main(const float* __restrict__ features, const float* __restrict__ aW1,
       const float* __restrict__ ab1, const float* __restrict__ aW2,
       const float* __restrict__ ab2, float* __restrict__ out) {
    extern __shared__ char smem[];
    __nv_bfloat16* sWt = (__nv_bfloat16*)(smem + OFF_SWT);   // [128][520] W^T (n-major)
    __nv_bfloat16* sA  = (__nv_bfloat16*)(smem + OFF_SA);    // [32][520] row tile
    float* sPart = (float*)(smem + OFF_PART);                // [32][4]
    float* sAttn = (float*)(smem + OFF_ATTN);                // [32]
    float* sBase = (float*)(smem + OFF_BASE);                // [128]
    float* sW2   = (float*)(smem + OFF_W2);                  // [128]
    float* sTot  = (float*)(smem + OFF_TOT);

    int tid = threadIdx.x;

    // Load W = aW1[D:2D, :] transposed into smem as bf16 (coalesced global reads)
    for (int idx = tid; idx < D * H; idx += THREADS1) {
        int k = idx >> 7, n = idx & 127;
        sWt[n * SWT_STR + k] = __float2bfloat16(aW1[(D + k) * H + n]);
    }
    for (int j = tid; j < H; j += THREADS1) {
        float s = ab1[j];
#pragma unroll
        for (int b = 0; b < 16; b++) s += g_basep[b * H + j];
        sBase[j] = s;
        sW2[j] = aW2[j];
    }
    if (tid == 0) *sTot = 0.f;
    __syncthreads();

    int warp = tid >> 5, lane = tid & 31;
    int g = lane >> 2, tg = lane & 3;
    int wm = warp >> 2, wn = warp & 3;    // 2 m-groups(16 rows) x 4 n-groups(32 cols)

    // ldmatrix base addresses (byte offsets in shared space)
    unsigned sA_u = (unsigned)__cvta_generic_to_shared(sA);
    unsigned sW_u = (unsigned)__cvta_generic_to_shared(sWt);
    unsigned aAddr = sA_u + (unsigned)(((wm * 16 + (lane & 15)) * SA_STR + ((lane >> 4) << 3)) * 2);
    int brow = wn * 32 + ((lane >> 4) << 3) + (lane & 7);
    int bk = ((lane >> 3) & 1) << 3;
    unsigned bAddr0 = sW_u + (unsigned)((brow * SWT_STR + bk) * 2);
    unsigned bAddr1 = bAddr0 + 16 * SWT_STR * 2;

    // hoist this thread's 8 (base, w2) column values
    float baseR[8], w2R[8];
#pragma unroll
    for (int nt = 0; nt < 4; nt++) {
        int col = wn * 32 + nt * 8 + tg * 2;
        baseR[nt * 2] = sBase[col];     baseR[nt * 2 + 1] = sBase[col + 1];
        w2R[nt * 2]   = sW2[col];       w2R[nt * 2 + 1]   = sW2[col + 1];
    }
    float ab2v = ab2[0];
    float agg0 = 0.f, agg1 = 0.f;       // this thread's agg columns: 2*tid, 2*tid+1

    int c4 = tid & 127;                 // this thread's float4 column
    int rhalf = tid >> 7;               // 0/1 -> even/odd tile rows

    // ---- prologue: prefetch first tile into registers ----
    float4 v[16];
    {
        long rowbase = (long)blockIdx.x * MBLK;
#pragma unroll
        for (int t = 0; t < 16; t++) {
            long prow = rowbase + 2 * t + rhalf;
            if (prow < NROW)
                v[t] = __ldcs((const float4*)(features + (prow + 1) * (long)D) + c4);
            else
                v[t] = make_float4(0.f, 0.f, 0.f, 0.f);
        }
    }

    for (int blk = blockIdx.x; blk < NBLK; blk += gridDim.x) {
        long rowbase = (long)blk * MBLK;

        __syncthreads();   // previous consumers of sA/sAttn are done

        // ---- drain registers: copy to out + bf16 tile in smem ----
#pragma unroll
        for (int t = 0; t < 16; t++) {
            int r = 2 * t + rhalf;
            long prow = rowbase + r;
            float4 w = v[t];
            if (prow < NROW)
                __stcs((float4*)(out + (prow + 1) * (long)D) + c4, w);
            __nv_bfloat162 lo = __floats2bfloat162_rn(w.x, w.y);
            __nv_bfloat162 hi = __floats2bfloat162_rn(w.z, w.w);
            uint2 pk;
            pk.x = *(unsigned*)&lo; pk.y = *(unsigned*)&hi;
            *(uint2*)(sA + r * SA_STR + c4 * 4) = pk;
        }

        // ---- prefetch next tile (overlaps with GEMM below) ----
        long nextbase = rowbase + (long)gridDim.x * MBLK;
        if (nextbase < NROW) {
#pragma unroll
            for (int t = 0; t < 16; t++) {
                long prow = nextbase + 2 * t + rhalf;
                if (prow < NROW)
                    v[t] = __ldcs((const float4*)(features + (prow + 1) * (long)D) + c4);
                else
                    v[t] = make_float4(0.f, 0.f, 0.f, 0.f);
            }
        }
        __syncthreads();   // sA tile ready

        // ---- GEMM: (32 x 512) @ (512 x 128), warp tile 16x32, ldmatrix ----
        float c[4][4];
#pragma unroll
        for (int nt = 0; nt < 4; nt++)
#pragma unroll
            for (int q = 0; q < 4; q++) c[nt][q] = 0.f;

#pragma unroll 4
        for (int k0 = 0; k0 < D; k0 += 16) {
            unsigned aF[4], b0[4], b1[4];
            ldsm4(aF, aAddr + k0 * 2);
            ldsm4(b0, bAddr0 + k0 * 2);
            ldsm4(b1, bAddr1 + k0 * 2);
            mma16816(c[0], aF, b0[0], b0[1]);
            mma16816(c[1], aF, b0[2], b0[3]);
            mma16816(c[2], aF, b1[0], b1[1]);
            mma16816(c[3], aF, b1[2], b1[3]);
        }

        // ---- epilogue: per-row partial  sum_cols relu(base+h)*w2 ----
        {
            float pe = 0.f, po = 0.f;
#pragma unroll
            for (int nt = 0; nt < 4; nt++) {
                pe += fmaxf(baseR[nt * 2]     + c[nt][0], 0.f) * w2R[nt * 2];
                pe += fmaxf(baseR[nt * 2 + 1] + c[nt][1], 0.f) * w2R[nt * 2 + 1];
                po += fmaxf(baseR[nt * 2]     + c[nt][2], 0.f) * w2R[nt * 2];
                po += fmaxf(baseR[nt * 2 + 1] + c[nt][3], 0.f) * w2R[nt * 2 + 1];
            }
            pe += __shfl_xor_sync(0xffffffffu, pe, 1);
            pe += __shfl_xor_sync(0xffffffffu, pe, 2);
            po += __shfl_xor_sync(0xffffffffu, po, 1);
            po += __shfl_xor_sync(0xffffffffu, po, 2);
            if (tg == 0) {
                int row = wm * 16 + g;
                sPart[row * 4 + wn] = pe;
                sPart[(row + 8) * 4 + wn] = po;
            }
        }
        __syncthreads();

        // ---- attn = sigmoid(. + ab2), masked tail; fixed-order total ----
        if (tid < 32) {
            float s = sPart[tid * 4] + sPart[tid * 4 + 1] + sPart[tid * 4 + 2]
                    + sPart[tid * 4 + 3] + ab2v;
            float a = 1.f / (1.f + __expf(-s));
            if (rowbase + tid >= NROW) a = 0.f;
            sAttn[tid] = a;
            float vv = a;
#pragma unroll
            for (int o = 16; o; o >>= 1) vv += __shfl_xor_sync(0xffffffffu, vv, o);
            if (tid == 0) *sTot += vv;
        }
        __syncthreads();

        // ---- agg += attn_r * row_r  (this thread: cols 2*tid, 2*tid+1) ----
#pragma unroll 8
        for (int r = 0; r < MBLK; r++) {
            float a = sAttn[r];
            __nv_bfloat162 p = *(__nv_bfloat162*)(sA + r * SA_STR + tid * 2);
            agg0 += a * __bfloat162float(p.x);
            agg1 += a * __bfloat162float(p.y);
        }
    }

    g_aggp[blockIdx.x * D + 2 * tid]     = agg0;
    g_aggp[blockIdx.x * D + 2 * tid + 1] = agg1;
    if (tid == 0) g_attnp[blockIdx.x] = *sTot;
}

// ---------------- K2: reduce partials, build comb = [target, agg/s] ----------------
__global__ void k_reduce(const float* __restrict__ features) {
    __shared__ float sS;
    int j = threadIdx.x;   // 512
    float acc = 0.f;
    for (int i = 0; i < GRID1; i++) acc += g_aggp[i * D + j];
    if (j == 0) {
        float s = 0.f;
        for (int i = 0; i < GRID1; i++) s += g_attnp[i];
        sS = s;
    }
    __syncthreads();
    float s = sS;
    g_comb[j] = features[j];                       // target
    g_comb[D + j] = (s > 0.f) ? acc / s : acc;     // agg
}

// ---------------- K3: partial dots for gate (gW) and hidden (uW1) ----------------
__global__ void k_mid(const float* __restrict__ gW, const float* __restrict__ uW1) {
    __shared__ float sc[128];
    int b = blockIdx.x;                 // 64 blocks: mat(2) x kchunk(8) x colchunk(4)
    int mat = b >> 5, kc = (b >> 2) & 7, cc = b & 3;
    const float* W = mat ? uW1 : gW;
    int ks = kc * 128;
    if (threadIdx.x < 128) sc[threadIdx.x] = g_comb[ks + threadIdx.x];
    __syncthreads();
    int col = cc * 128 + threadIdx.x;   // 128 threads
    float a = 0.f;
#pragma unroll 4
    for (int kk = 0; kk < 128; kk++) a += sc[kk] * W[(ks + kk) * D + col];
    g_p3[(mat * 8 + kc) * D + col] = a;
}

// ---------------- K4: gate = sigmoid(.+gb), hidden = relu(.+ub1) ----------------
__global__ void k_act(const float* __restrict__ gb, const float* __restrict__ ub1) {
    int j = threadIdx.x;   // 512
    float gs = 0.f, hs = 0.f;
    for (int b = 0; b < 8; b++)  gs += g_p3[b * D + j];
    for (int b = 8; b < 16; b++) hs += g_p3[b * D + j];
    g_gate[j] = 1.f / (1.f + __expf(-(gs + gb[j])));
    g_hidden[j] = fmaxf(hs + ub1[j], 0.f);
}

// ---------------- K5: partial dots for upd (uW2) ----------------
__global__ void k_upd(const float* __restrict__ uW2) {
    __shared__ float sh[64];
    int b = blockIdx.x;       // 32 blocks: kchunk(8) x colchunk(4)
    int kc = b >> 2, cc = b & 3;
    int ks = kc * 64;
    if (threadIdx.x < 64) sh[threadIdx.x] = g_hidden[ks + threadIdx.x];
    __syncthreads();
    int col = cc * 128 + threadIdx.x;   // 128 threads
    float a = 0.f;
#pragma unroll 4
    for (int kk = 0; kk < 64; kk++) a += sh[kk] * uW2[(ks + kk) * D + col];
    g_p5[kc * D + col] = a;
}

// ---------------- K6: out row 0 = target + gate * (upd + ub2) ----------------
__global__ void k_fin(const float* __restrict__ features, const float* __restrict__ ub2,
                      float* __restrict__ out) {
    int j = threadIdx.x;   // 512
    float u = 0.f;
    for (int b = 0; b < 8; b++) u += g_p5[b * D + j];
    u += ub2[0];
    out[j] = features[j] + g_gate[j] * u;
}

extern "C" void kernel_launch(void* const* d_in, const int* in_sizes, int n_in,
                              void* d_out, int out_size) {
    const float* features = (const float*)d_in[0];
    const float* aW1 = (const float*)d_in[1];
    const float* ab1 = (const float*)d_in[2];
    const float* aW2 = (const float*)d_in[3];
    const float* ab2 = (const float*)d_in[4];
    const float* uW1 = (const float*)d_in[5];
    const float* ub1 = (const float*)d_in[6];
    const float* uW2 = (const float*)d_in[7];
    const float* ub2 = (const float*)d_in[8];
    const float* gW  = (const float*)d_in[9];
    const float* gb  = (const float*)d_in[10];
    float* out = (float*)d_out;

    cudaFuncSetAttribute(k_main, cudaFuncAttributeMaxDynamicSharedMemorySize, SMEM_SZ);

    k_basep<<<16, 128>>>(features, aW1);
    k_main<<<GRID1, THREADS1, SMEM_SZ>>>(features, aW1, ab1, aW2, ab2, out);
    k_reduce<<<1, 512>>>(features);
    k_mid<<<64, 128>>>(gW, uW1);
    k_act<<<1, 512>>>(gb, ub1);
    k_upd<<<32, 128>>>(uW2);
    k_fin<<<1, 512>>>(features, ub2, out);
}